// round 16
// baseline (speedup 1.0000x reference)
#include <cuda_runtime.h>
#include <math.h>
#include <float.h>
#include <stdint.h>

#define BB 16
#define CC 64
#define NN 16384
#define SS 64            // NUM_NODE
#define KK 64            // NSAMPLE
#define BN_CNT 262144    // B*N
#define NCOV 256

// output packing: [output_fea (16,128,16384,1) | node_fea (16,64,64,1) | node_offset (16,3,64)]
#define OFF_NF 33554432
#define OFF_NO 33619968

// ---------------- scratch (device globals; no allocations allowed) ----------------
__device__ float g_feaT[BB * NN * CC];       // 64 MB  feaT[b][n][c]
__device__ int   g_fidx[BB * SS];
__device__ float g_fploc[BB * 3 * SS];       // [b][o][s]
__device__ float g_fpfea[BB * CC * SS];      // [b][c][s]
__device__ int   g_gidx[BB * SS * KK];
__device__ float g_nodeloc[BB * 3 * SS];
__device__ float g_nodesq[BB * SS];
__device__ float g_covpart[NCOV * 4096];
__device__ float g_meanpart[NCOV * 64];
__device__ float g_cov[4096];
__device__ float g_meansum[64];
__device__ float g_A[64];
__device__ float g_Bc[64];

__device__ __forceinline__ float sq3(float a, float b, float c) {
    // ((a*a + b*b) + c*c) with no FMA contraction (elementwise+reduce HLO is not contracted)
    return __fadd_rn(__fadd_rn(__fmul_rn(a, a), __fmul_rn(b, b)), __fmul_rn(c, c));
}
// einsum/dot_general path: ascending-k FMA chain (matches XLA fmuladd / Eigen / cuBLAS)
__device__ __forceinline__ float dot3fma(float ax, float ay, float az,
                                         float bx, float by, float bz) {
    return __fmaf_rn(az, bz, __fmaf_rn(ay, by, __fmul_rn(ax, bx)));
}

// ---------------- K1: farthest point sampling (one block per batch) ----------------
__global__ __launch_bounds__(1024) void fps_kernel(const float* __restrict__ loc,
                                                   const float* __restrict__ fea) {
    extern __shared__ float sh[];                 // x[N], y[N], z[N]
    float* shx = sh;
    float* shy = sh + NN;
    float* shz = sh + 2 * NN;
    __shared__ float swv[32];
    __shared__ int   swi[32];
    __shared__ int   s_far;
    __shared__ int   s_fidx[SS];

    int b = blockIdx.x, tid = threadIdx.x;
    const float* lb = loc + (size_t)b * 3 * NN;
    for (int p = tid; p < NN; p += 1024) {
        shx[p] = lb[p];
        shy[p] = lb[NN + p];
        shz[p] = lb[2 * NN + p];
    }
    float dist[16];
#pragma unroll
    for (int i = 0; i < 16; i++) dist[i] = 1e10f;
    if (tid == 0) { s_far = 0; s_fidx[0] = 0; }
    __syncthreads();

    for (int it = 0; it < SS - 1; it++) {
        int far = s_far;
        float cx = shx[far], cy = shy[far], cz = shz[far];
        float bestv = -1.0f;
        int   besti = 0;
#pragma unroll
        for (int i = 0; i < 16; i++) {
            int p = tid + i * 1024;
            float dx = shx[p] - cx, dy = shy[p] - cy, dz = shz[p] - cz;
            float d = sq3(dx, dy, dz);
            float nd = fminf(dist[i], d);
            dist[i] = nd;
            if (nd > bestv) { bestv = nd; besti = p; }   // ascending p: strict > keeps lowest idx
        }
        unsigned lane = tid & 31, w = tid >> 5;
#pragma unroll
        for (int off = 16; off; off >>= 1) {
            float ov = __shfl_down_sync(0xffffffffu, bestv, off);
            int   oi = __shfl_down_sync(0xffffffffu, besti, off);
            if (ov > bestv || (ov == bestv && oi < besti)) { bestv = ov; besti = oi; }
        }
        if (lane == 0) { swv[w] = bestv; swi[w] = besti; }
        __syncthreads();
        if (tid == 0) {
            float bv = swv[0]; int bi = swi[0];
            for (int k = 1; k < 32; k++)
                if (swv[k] > bv || (swv[k] == bv && swi[k] < bi)) { bv = swv[k]; bi = swi[k]; }
            s_far = bi;
            s_fidx[it + 1] = bi;
        }
        __syncthreads();
    }
    if (tid < SS) g_fidx[b * SS + tid] = s_fidx[tid];
    if (tid < 3 * SS) {
        int o = tid / SS, s = tid % SS;
        g_fploc[(b * 3 + o) * SS + s] = lb[o * NN + s_fidx[s]];
    }
    const float* fb = fea + (size_t)b * CC * NN;
    for (int j = tid; j < CC * SS; j += 1024) {
        int c = j >> 6, s = j & 63;
        g_fpfea[(b * CC + c) * SS + s] = fb[c * NN + s_fidx[s]];
    }
}

// ---------------- K2: transpose fea (B,C,N) -> feaT (B,N,C) ----------------
__global__ void transpose_kernel(const float* __restrict__ fea) {
    __shared__ float t[32][33];
    int b = blockIdx.z;
    int c0 = blockIdx.y * 32, n0 = blockIdx.x * 32;
    int tx = threadIdx.x, ty = threadIdx.y;   // (32,8)
    const float* fb = fea + (size_t)b * CC * NN;
    float* ob = g_feaT + (size_t)b * NN * CC;
#pragma unroll
    for (int i = 0; i < 32; i += 8) t[ty + i][tx] = fb[(c0 + ty + i) * NN + n0 + tx];
    __syncthreads();
#pragma unroll
    for (int i = 0; i < 32; i += 8) ob[(n0 + ty + i) * CC + c0 + tx] = t[tx][ty + i];
}

// ---------------- K3: feature second moment (64x64 SYRK, K=262144) ----------------
__global__ __launch_bounds__(64) void cov_kernel() {
    __shared__ float sh[32][72];
    int tid = threadIdx.x;
    int ty = tid >> 3, tx = tid & 7;
    float acc[8][8];
#pragma unroll
    for (int i = 0; i < 8; i++)
#pragma unroll
        for (int j = 0; j < 8; j++) acc[i][j] = 0.f;
    float msum = 0.f;
    int base = blockIdx.x * 1024;   // global point index (b*N+n flattens into feaT rows)
    for (int t0 = 0; t0 < 1024; t0 += 32) {
        __syncthreads();
        for (int idx = tid; idx < 512; idx += 64) {
            int p = idx >> 4, seg = idx & 15;
            float4 v = *(const float4*)(g_feaT + (size_t)(base + t0 + p) * CC + seg * 4);
            *(float4*)&sh[p][seg * 4] = v;
        }
        __syncthreads();
#pragma unroll 4
        for (int p = 0; p < 32; p++) {
            float a[8], bb[8];
            *(float4*)(a)      = *(float4*)&sh[p][8 * ty];
            *(float4*)(a + 4)  = *(float4*)&sh[p][8 * ty + 4];
            *(float4*)(bb)     = *(float4*)&sh[p][8 * tx];
            *(float4*)(bb + 4) = *(float4*)&sh[p][8 * tx + 4];
#pragma unroll
            for (int i = 0; i < 8; i++)
#pragma unroll
                for (int j = 0; j < 8; j++) acc[i][j] += a[i] * bb[j];
            msum += sh[p][tid];
        }
    }
    float* cp = g_covpart + blockIdx.x * 4096;
#pragma unroll
    for (int i = 0; i < 8; i++)
#pragma unroll
        for (int j = 0; j < 8; j++) cp[(8 * ty + i) * 64 + 8 * tx + j] = acc[i][j];
    g_meanpart[blockIdx.x * 64 + tid] = msum;
}

// deterministic reduction of partials
__global__ void cov_reduce_kernel() {
    int e = blockIdx.x * 256 + threadIdx.x;
    if (e < 4096) {
        float s = 0.f;
        for (int k = 0; k < NCOV; k++) s += g_covpart[k * 4096 + e];
        g_cov[e] = s;
    } else if (e < 4160) {
        int c = e - 4096;
        float s = 0.f;
        for (int k = 0; k < NCOV; k++) s += g_meanpart[k * 64 + c];
        g_meansum[c] = s;
    }
}

// ---------------- K4: fold BN stats into affine A*y + Bc ----------------
__global__ void bn_kernel(const float* __restrict__ w, const float* __restrict__ bres,
                          const float* __restrict__ gres, const float* __restrict__ beres) {
    int o = threadIdx.x;   // 64
    const float invBN = 1.0f / (float)BN_CNT;
    float wm = 0.f;
    for (int c = 0; c < 64; c++) wm += w[o * 64 + c] * g_meansum[c];
    float meany = wm * invBN + bres[o];
    float wMw = 0.f;
    for (int c = 0; c < 64; c++) {
        float t = 0.f;
        for (int c2 = 0; c2 < 64; c2++) t += w[o * 64 + c2] * g_cov[c * 64 + c2];
        wMw += w[o * 64 + c] * t;
    }
    float Ey2 = wMw * invBN + 2.f * bres[o] * (wm * invBN) + bres[o] * bres[o];
    float var = Ey2 - meany * meany;
    float A = gres[o] * (1.0f / sqrtf(var + 1e-5f));
    g_A[o] = A;
    g_Bc[o] = beres[o] - meany * A;
}

// ---------------- K5: radius ball query (lowest-index hits, warp per center) ----------------
__global__ __launch_bounds__(128) void ball_kernel(const float* __restrict__ loc) {
    int gw = blockIdx.x * 4 + (threadIdx.x >> 5);   // 0..1023
    int lane = threadIdx.x & 31;
    int b = gw >> 6, s = gw & 63;
    const float* lb = loc + (size_t)b * 3 * NN;
    float cx = g_fploc[(b * 3 + 0) * SS + s];
    float cy = g_fploc[(b * 3 + 1) * SS + s];
    float cz = g_fploc[(b * 3 + 2) * SS + s];
    float ss = sq3(cx, cy, cz);
    int* gi = g_gidx + (b * SS + s) * KK;
    int total = 0;
    for (int n0 = 0; n0 < NN; n0 += 32) {
        int p = n0 + lane;
        float x = lb[p], y = lb[NN + p], z = lb[2 * NN + p];
        float sq = __fadd_rn(__fadd_rn(__fmul_rn(-2.0f, dot3fma(cx, cy, cz, x, y, z)), ss),
                             sq3(x, y, z));
        bool hit = !(sq > 0.09f);
        unsigned m = __ballot_sync(0xffffffffu, hit);
        int pos = total + __popc(m & ((1u << lane) - 1u));
        if (hit && pos < KK) gi[pos] = p;
        total += __popc(m);
        if (total >= KK) break;
    }
    __syncwarp();
    if (total < KK) {
        int first = (total > 0) ? gi[0] : 0;
        for (int j = total + lane; j < KK; j += 32) gi[j] = first;
    }
}

// ---------------- K6: node offset / node loc (block per (b,s), thread per k) ----------------
__global__ __launch_bounds__(64) void node_kernel(const float* __restrict__ loc,
                                                  const float* __restrict__ woff,
                                                  float* __restrict__ out) {
    int b = blockIdx.x >> 6, s = blockIdx.x & 63;
    int k = threadIdx.x;   // 64
    __shared__ float swoff[192];
    __shared__ float sfpf[64];
    __shared__ float part[6];
    sfpf[k] = g_fpfea[(b * CC + k) * SS + s];
    for (int j = k; j < 192; j += 64) swoff[j] = woff[j];
    __syncthreads();

    int p = g_gidx[(b * SS + s) * KK + k];
    const float* lb = loc + (size_t)b * 3 * NN;
    float flx = g_fploc[(b * 3 + 0) * SS + s];
    float fly = g_fploc[(b * 3 + 1) * SS + s];
    float flz = g_fploc[(b * 3 + 2) * SS + s];
    float dlx = lb[p] - flx, dly = lb[NN + p] - fly, dlz = lb[2 * NN + p] - flz;

    const float* fr = g_feaT + ((size_t)b * NN + p) * CC;
    float s0 = 0.f, s1 = 0.f, s2 = 0.f;
#pragma unroll
    for (int c = 0; c < 64; c++) {
        float df = fr[c] - sfpf[c];
        s0 += swoff[c] * df;
        s1 += swoff[64 + c] * df;
        s2 += swoff[128 + c] * df;
    }
    float t0 = tanhf(s0) * dlx, t1 = tanhf(s1) * dly, t2 = tanhf(s2) * dlz;
    unsigned lane = k & 31, w = k >> 5;
#pragma unroll
    for (int off = 16; off; off >>= 1) {
        t0 += __shfl_down_sync(0xffffffffu, t0, off);
        t1 += __shfl_down_sync(0xffffffffu, t1, off);
        t2 += __shfl_down_sync(0xffffffffu, t2, off);
    }
    if (lane == 0) { part[w * 3 + 0] = t0; part[w * 3 + 1] = t1; part[w * 3 + 2] = t2; }
    __syncthreads();
    if (k == 0) {
        float m0 = (part[0] + part[3]) * (1.f / 64.f);
        float m1 = (part[1] + part[4]) * (1.f / 64.f);
        float m2 = (part[2] + part[5]) * (1.f / 64.f);
        out[OFF_NO + (b * 3 + 0) * SS + s] = m0;
        out[OFF_NO + (b * 3 + 1) * SS + s] = m1;
        out[OFF_NO + (b * 3 + 2) * SS + s] = m2;
        float nx = flx + m0, ny = fly + m1, nz = flz + m2;
        g_nodeloc[(b * 3 + 0) * SS + s] = nx;
        g_nodeloc[(b * 3 + 1) * SS + s] = ny;
        g_nodeloc[(b * 3 + 2) * SS + s] = nz;
        g_nodesq[b * SS + s] = sq3(nx, ny, nz);
    }
}

// ---------------- K7: fused 64-NN + residual-BN-ReLU + max (block per (b,s)) ----------------
__global__ __launch_bounds__(256) void nodefea_kernel(const float* __restrict__ loc,
                                                      const float* __restrict__ wres,
                                                      const float* __restrict__ bres,
                                                      float* __restrict__ out) {
    extern __shared__ float sd[];   // 16384 dists, later reused as gf[64][68]
    __shared__ int   sel[KK];
    __shared__ float swv[8];
    __shared__ int   swi[8];
    __shared__ float smax[256];

    int b = blockIdx.x >> 6, s = blockIdx.x & 63;
    int tid = threadIdx.x;
    const float* lb = loc + (size_t)b * 3 * NN;
    float nx = g_nodeloc[(b * 3 + 0) * SS + s];
    float ny = g_nodeloc[(b * 3 + 1) * SS + s];
    float nz = g_nodeloc[(b * 3 + 2) * SS + s];
    float nsq = g_nodesq[b * SS + s];

    for (int p = tid; p < NN; p += 256) {
        float x = lb[p], y = lb[NN + p], z = lb[2 * NN + p];
        sd[p] = __fadd_rn(__fadd_rn(__fmul_rn(-2.0f, dot3fma(nx, ny, nz, x, y, z)), nsq),
                          sq3(x, y, z));
    }
    __syncthreads();

    // 64 argmin rounds (set of 64 smallest; ties -> lowest index, matching stable argsort)
    for (int r = 0; r < KK; r++) {
        float bv = 3.402823466e38f;
        int   bi = 0x7fffffff;
#pragma unroll 8
        for (int j = 0; j < 64; j++) {
            int p = tid + (j << 8);
            float v = sd[p];
            if (v < bv) { bv = v; bi = p; }   // ascending p per thread
        }
        unsigned lane = tid & 31, w = tid >> 5;
#pragma unroll
        for (int off = 16; off; off >>= 1) {
            float ov = __shfl_down_sync(0xffffffffu, bv, off);
            int   oi = __shfl_down_sync(0xffffffffu, bi, off);
            if (ov < bv || (ov == bv && oi < bi)) { bv = ov; bi = oi; }
        }
        if (lane == 0) { swv[w] = bv; swi[w] = bi; }
        __syncthreads();
        if (tid == 0) {
            float fv = swv[0]; int fi = swi[0];
            for (int k = 1; k < 8; k++)
                if (swv[k] < fv || (swv[k] == fv && swi[k] < fi)) { fv = swv[k]; fi = swi[k]; }
            sel[r] = fi;
            sd[fi] = 3.402823466e38f;
        }
        __syncthreads();
    }

    // phase C: gather features of the 64 selected points (point-contiguous rows), GEMV, max
    float* gf = sd;   // [64][68]
    int o = tid & 63, kq = tid >> 6;
    float wr[64];
    const float4* wp = (const float4*)(wres + o * 64);
#pragma unroll
    for (int i = 0; i < 16; i++) ((float4*)wr)[i] = wp[i];

    for (int idx = tid; idx < 1024; idx += 256) {
        int k = idx >> 4, seg = idx & 15;
        int p = sel[k];
        float4 v = *(const float4*)(g_feaT + ((size_t)b * NN + p) * CC + seg * 4);
        *(float4*)&gf[k * 68 + seg * 4] = v;
    }
    __syncthreads();

    float A = g_A[o], Bc = g_Bc[o], bv0 = bres[o];
    float mx = -3.402823466e38f;
    for (int j = 0; j < 16; j++) {
        int k = kq * 16 + j;
        const float* g = &gf[k * 68];
        float y = 0.f;
#pragma unroll
        for (int c = 0; c < 64; c++) y += wr[c] * g[c];
        float v = fmaxf(0.f, A * (y + bv0) + Bc);
        mx = fmaxf(mx, v);
    }
    smax[tid] = mx;
    __syncthreads();
    if (tid < 64) {
        float m = fmaxf(fmaxf(smax[tid], smax[tid + 64]), fmaxf(smax[tid + 128], smax[tid + 192]));
        out[OFF_NF + (b * CC + tid) * SS + s] = m;
    }
}

// ---------------- K8: 3-NN inverse-distance interpolation + concat copy ----------------
__global__ __launch_bounds__(256) void upsample_kernel(const float* __restrict__ loc,
                                                       const float* __restrict__ fea,
                                                       float* __restrict__ out) {
    __shared__ float snx[64], sny[64], snz[64], snq[64];
    __shared__ float snf[64 * 68];   // [m][c], pad 68
    int b = blockIdx.y;
    int n = blockIdx.x * 256 + threadIdx.x;
    int tid = threadIdx.x;
    if (tid < 64) {
        snx[tid] = g_nodeloc[(b * 3 + 0) * SS + tid];
        sny[tid] = g_nodeloc[(b * 3 + 1) * SS + tid];
        snz[tid] = g_nodeloc[(b * 3 + 2) * SS + tid];
        snq[tid] = g_nodesq[b * SS + tid];
    }
    for (int idx = tid; idx < 4096; idx += 256) {
        int m = idx & 63, c = idx >> 6;
        snf[m * 68 + c] = out[OFF_NF + (b * CC + c) * SS + m];
    }
    __syncthreads();

    const float* lb = loc + (size_t)b * 3 * NN;
    float x = lb[n], y = lb[NN + n], z = lb[2 * NN + n];
    float psq = sq3(x, y, z);

    float d0 = 3.402823466e38f, d1 = d0, d2 = d0;
    int i0 = 0, i1 = 0, i2 = 0;
#pragma unroll 8
    for (int m = 0; m < 64; m++) {
        float d = __fadd_rn(
            __fadd_rn(__fmul_rn(-2.0f, dot3fma(x, y, z, snx[m], sny[m], snz[m])), psq),
            snq[m]);
        if (d < d0)      { d2 = d1; i2 = i1; d1 = d0; i1 = i0; d0 = d; i0 = m; }
        else if (d < d1) { d2 = d1; i2 = i1; d1 = d; i1 = m; }
        else if (d < d2) { d2 = d; i2 = m; }
    }
    float w0 = 1.0f / fmaxf(d0, 1e-10f);
    float w1 = 1.0f / fmaxf(d1, 1e-10f);
    float w2 = 1.0f / fmaxf(d2, 1e-10f);
    float wsum = w0 + w1 + w2;
    w0 /= wsum; w1 /= wsum; w2 /= wsum;

    const float* fb = fea + (size_t)b * CC * NN;
    float* ob = out + (size_t)b * 128 * NN;
#pragma unroll 8
    for (int c = 0; c < 64; c++) {
        float ip = snf[i0 * 68 + c] * w0 + snf[i1 * 68 + c] * w1 + snf[i2 * 68 + c] * w2;
        ob[(64 + c) * NN + n] = ip;
        ob[c * NN + n] = fb[c * NN + n];
    }
}

// ---------------- launch ----------------
extern "C" void kernel_launch(void* const* d_in, const int* in_sizes, int n_in,
                              void* d_out, int out_size) {
    const float* fea   = (const float*)d_in[0];
    const float* loc   = (const float*)d_in[1];
    const float* wres  = (const float*)d_in[2];
    const float* bres  = (const float*)d_in[3];
    const float* gres  = (const float*)d_in[4];
    const float* beres = (const float*)d_in[5];
    const float* woff  = (const float*)d_in[6];
    float* out = (float*)d_out;

    cudaFuncSetAttribute(fps_kernel, cudaFuncAttributeMaxDynamicSharedMemorySize, 3 * NN * 4);
    cudaFuncSetAttribute(nodefea_kernel, cudaFuncAttributeMaxDynamicSharedMemorySize, NN * 4);

    fps_kernel<<<BB, 1024, 3 * NN * 4>>>(loc, fea);
    transpose_kernel<<<dim3(NN / 32, CC / 32, BB), dim3(32, 8)>>>(fea);
    cov_kernel<<<NCOV, 64>>>();
    cov_reduce_kernel<<<17, 256>>>();
    bn_kernel<<<1, 64>>>(wres, bres, gres, beres);
    ball_kernel<<<256, 128>>>(loc);
    node_kernel<<<BB * SS, 64>>>(loc, woff, out);
    nodefea_kernel<<<BB * SS, 256, NN * 4>>>(loc, wres, bres, out);
    upsample_kernel<<<dim3(NN / 256, BB), 256>>>(loc, fea, out);
}

// round 17
// speedup vs baseline: 1.2291x; 1.2291x over previous
#include <cuda_runtime.h>
#include <math.h>
#include <float.h>
#include <stdint.h>

#define BB 16
#define CC 64
#define NN 16384
#define SS 64            // NUM_NODE
#define KK 64            // NSAMPLE
#define BN_CNT 262144    // B*N
#define NCOV 256

// output packing: [output_fea (16,128,16384,1) | node_fea (16,64,64,1) | node_offset (16,3,64)]
#define OFF_NF 33554432
#define OFF_NO 33619968

// ---------------- scratch (device globals; no allocations allowed) ----------------
__device__ float g_feaT[BB * NN * CC];       // 64 MB  feaT[b][n][c]
__device__ float g_fploc[BB * 3 * SS];       // [b][o][s]
__device__ float g_fpfea[BB * CC * SS];      // [b][c][s]
__device__ int   g_gidx[BB * SS * KK];
__device__ float g_nodeloc[BB * 3 * SS];
__device__ float g_nodesq[BB * SS];
__device__ float g_covpart[NCOV * 4096];
__device__ float g_meanpart[NCOV * 64];
__device__ float g_cov2[8 * 4096];
__device__ float g_mean2[8 * 64];
__device__ float g_cov[4096];
__device__ float g_meansum[64];
__device__ float g_A[64];
__device__ float g_Bc[64];

__device__ __forceinline__ float sq3(float a, float b, float c) {
    // ((a*a + b*b) + c*c) with no FMA contraction (elementwise+reduce HLO is not contracted)
    return __fadd_rn(__fadd_rn(__fmul_rn(a, a), __fmul_rn(b, b)), __fmul_rn(c, c));
}
// einsum/dot_general path: ascending-k FMA chain (matches XLA fmuladd / Eigen / cuBLAS)
__device__ __forceinline__ float dot3fma(float ax, float ay, float az,
                                         float bx, float by, float bz) {
    return __fmaf_rn(az, bz, __fmaf_rn(ay, by, __fmul_rn(ax, bx)));
}

// packed f32x2 helpers (sm_100+)
__device__ __forceinline__ unsigned long long fma2(unsigned long long a,
                                                   unsigned long long b,
                                                   unsigned long long c) {
    unsigned long long d;
    asm("fma.rn.f32x2 %0, %1, %2, %3;" : "=l"(d) : "l"(a), "l"(b), "l"(c));
    return d;
}
__device__ __forceinline__ unsigned long long pack2(float x, float y) {
    unsigned long long r;
    asm("mov.b64 %0, {%1, %2};" : "=l"(r) : "f"(x), "f"(y));
    return r;
}
__device__ __forceinline__ void unpack2(unsigned long long v, float& lo, float& hi) {
    asm("mov.b64 {%0, %1}, %2;" : "=f"(lo), "=f"(hi) : "l"(v));
}

// ---------------- K1: farthest point sampling (one block per batch) ----------------
__global__ __launch_bounds__(1024) void fps_kernel(const float* __restrict__ loc,
                                                   const float* __restrict__ fea) {
    extern __shared__ float sh[];                 // x[N], y[N], z[N]
    float* shx = sh;
    float* shy = sh + NN;
    float* shz = sh + 2 * NN;
    __shared__ float swv[32];
    __shared__ int   swi[32];
    __shared__ int   s_far;
    __shared__ int   s_fidx[SS];

    int b = blockIdx.x, tid = threadIdx.x;
    const float* lb = loc + (size_t)b * 3 * NN;
    for (int p = tid; p < NN; p += 1024) {
        shx[p] = lb[p];
        shy[p] = lb[NN + p];
        shz[p] = lb[2 * NN + p];
    }
    float dist[16];
#pragma unroll
    for (int i = 0; i < 16; i++) dist[i] = 1e10f;
    if (tid == 0) { s_far = 0; s_fidx[0] = 0; }
    __syncthreads();

    for (int it = 0; it < SS - 1; it++) {
        int far = s_far;
        float cx = shx[far], cy = shy[far], cz = shz[far];
        float bestv = -1.0f;
        int   besti = 0;
#pragma unroll
        for (int i = 0; i < 16; i++) {
            int p = tid + i * 1024;
            float dx = shx[p] - cx, dy = shy[p] - cy, dz = shz[p] - cz;
            float d = sq3(dx, dy, dz);
            float nd = fminf(dist[i], d);
            dist[i] = nd;
            if (nd > bestv) { bestv = nd; besti = p; }   // ascending p: strict > keeps lowest idx
        }
        unsigned lane = tid & 31, w = tid >> 5;
#pragma unroll
        for (int off = 16; off; off >>= 1) {
            float ov = __shfl_down_sync(0xffffffffu, bestv, off);
            int   oi = __shfl_down_sync(0xffffffffu, besti, off);
            if (ov > bestv || (ov == bestv && oi < besti)) { bestv = ov; besti = oi; }
        }
        if (lane == 0) { swv[w] = bestv; swi[w] = besti; }
        __syncthreads();
        if (tid < 32) {
            float bv = swv[tid]; int bi = swi[tid];
#pragma unroll
            for (int off = 16; off; off >>= 1) {
                float ov = __shfl_down_sync(0xffffffffu, bv, off);
                int   oi = __shfl_down_sync(0xffffffffu, bi, off);
                if (ov > bv || (ov == bv && oi < bi)) { bv = ov; bi = oi; }
            }
            if (tid == 0) { s_far = bi; s_fidx[it + 1] = bi; }
        }
        __syncthreads();
    }
    if (tid < 3 * SS) {
        int o = tid / SS, s = tid % SS;
        g_fploc[(b * 3 + o) * SS + s] = lb[o * NN + s_fidx[s]];
    }
    const float* fb = fea + (size_t)b * CC * NN;
    for (int j = tid; j < CC * SS; j += 1024) {
        int c = j >> 6, s = j & 63;
        g_fpfea[(b * CC + c) * SS + s] = fb[c * NN + s_fidx[s]];
    }
}

// ---------------- K2: transpose fea (B,C,N) -> feaT (B,N,C) ----------------
__global__ void transpose_kernel(const float* __restrict__ fea) {
    __shared__ float t[32][33];
    int b = blockIdx.z;
    int c0 = blockIdx.y * 32, n0 = blockIdx.x * 32;
    int tx = threadIdx.x, ty = threadIdx.y;   // (32,8)
    const float* fb = fea + (size_t)b * CC * NN;
    float* ob = g_feaT + (size_t)b * NN * CC;
#pragma unroll
    for (int i = 0; i < 32; i += 8) t[ty + i][tx] = fb[(c0 + ty + i) * NN + n0 + tx];
    __syncthreads();
#pragma unroll
    for (int i = 0; i < 32; i += 8) ob[(n0 + ty + i) * CC + c0 + tx] = t[tx][ty + i];
}

// ---------------- K3: feature second moment (64x64 SYRK, K=262144) ----------------
// 256 threads = 4 k-groups of 64; each group: 8x8 register tile over its 256 points.
// Inner product uses packed fma.rn.f32x2 (2 FMA / inst).
__global__ __launch_bounds__(256) void cov_kernel() {
    __shared__ float sh[128 * 72];     // 36 KB staging: 128 points x 64 ch (pad 72)
    __shared__ float mm[256];
    int tid = threadIdx.x;
    int grp = tid >> 6;                // k-group 0..3
    int gt  = tid & 63;
    int ty = gt >> 3, tx = gt & 7;

    unsigned long long acc2[8][4];
#pragma unroll
    for (int i = 0; i < 8; i++)
#pragma unroll
        for (int j = 0; j < 4; j++) acc2[i][j] = 0ull;
    float msum = 0.f;

    int base = blockIdx.x * 1024;
    for (int c0 = 0; c0 < 1024; c0 += 128) {
        __syncthreads();
#pragma unroll
        for (int q = 0; q < 8; ++q) {
            int idx = tid + q * 256;
            int p = idx >> 4, seg = idx & 15;
            float4 v = *(const float4*)(g_feaT + (size_t)(base + c0 + p) * 64 + seg * 4);
            *(float4*)&sh[p * 72 + seg * 4] = v;
        }
        __syncthreads();
#pragma unroll 2
        for (int pp = 0; pp < 32; ++pp) {
            const float* row = &sh[(grp * 32 + pp) * 72];
            float a[8];
            *(float4*)(a)     = *(const float4*)(row + 8 * ty);
            *(float4*)(a + 4) = *(const float4*)(row + 8 * ty + 4);
            ulonglong2 bA = *(const ulonglong2*)(row + 8 * tx);
            ulonglong2 bB = *(const ulonglong2*)(row + 8 * tx + 4);
            unsigned long long bp0 = bA.x, bp1 = bA.y, bp2 = bB.x, bp3 = bB.y;
#pragma unroll
            for (int i = 0; i < 8; ++i) {
                unsigned long long ap = pack2(a[i], a[i]);
                acc2[i][0] = fma2(ap, bp0, acc2[i][0]);
                acc2[i][1] = fma2(ap, bp1, acc2[i][1]);
                acc2[i][2] = fma2(ap, bp2, acc2[i][2]);
                acc2[i][3] = fma2(ap, bp3, acc2[i][3]);
            }
            msum += row[gt];
        }
    }
    // combine the 4 group partials in smem (serialized, deterministic)
    __syncthreads();
    float* comb = sh;
    for (int g = 0; g < 4; ++g) {
        if (grp == g) {
#pragma unroll
            for (int i = 0; i < 8; ++i)
#pragma unroll
                for (int jp = 0; jp < 4; ++jp) {
                    float lo, hi;
                    unpack2(acc2[i][jp], lo, hi);
                    int o = (8 * ty + i) * 64 + 8 * tx + 2 * jp;
                    if (g == 0) { comb[o] = lo; comb[o + 1] = hi; }
                    else        { comb[o] += lo; comb[o + 1] += hi; }
                }
        }
        __syncthreads();
    }
    float* cp = g_covpart + blockIdx.x * 4096;
#pragma unroll
    for (int w = 0; w < 16; ++w) cp[w * 256 + tid] = comb[w * 256 + tid];
    mm[tid] = msum;
    __syncthreads();
    if (tid < 64)
        g_meanpart[blockIdx.x * 64 + tid] = mm[tid] + mm[tid + 64] + mm[tid + 128] + mm[tid + 192];
}

// two-stage deterministic reduction of partials (high thread count -> BW saturated)
__global__ void covred1_kernel() {
    int gtid = blockIdx.x * 256 + threadIdx.x;
    if (gtid < 32768) {
        int e = gtid & 4095, g = gtid >> 12;
        float s = 0.f;
#pragma unroll 4
        for (int k = g * 32; k < g * 32 + 32; ++k) s += g_covpart[k * 4096 + e];
        g_cov2[g * 4096 + e] = s;
    } else if (gtid < 33280) {
        int t = gtid - 32768;
        int c = t & 63, g = t >> 6;
        float s = 0.f;
#pragma unroll 4
        for (int k = g * 32; k < g * 32 + 32; ++k) s += g_meanpart[k * 64 + c];
        g_mean2[g * 64 + c] = s;
    }
}
__global__ void covred2_kernel() {
    int e = blockIdx.x * 256 + threadIdx.x;
    if (e < 4096) {
        float s = 0.f;
#pragma unroll
        for (int g = 0; g < 8; ++g) s += g_cov2[g * 4096 + e];
        g_cov[e] = s;
    } else if (e < 4160) {
        int c = e - 4096;
        float s = 0.f;
#pragma unroll
        for (int g = 0; g < 8; ++g) s += g_mean2[g * 64 + c];
        g_meansum[c] = s;
    }
}

// ---------------- K4: fold BN stats into affine A*y + Bc ----------------
__global__ void bn_kernel(const float* __restrict__ w, const float* __restrict__ bres,
                          const float* __restrict__ gres, const float* __restrict__ beres) {
    int o = threadIdx.x;   // 64
    const float invBN = 1.0f / (float)BN_CNT;
    float wm = 0.f;
    for (int c = 0; c < 64; c++) wm += w[o * 64 + c] * g_meansum[c];
    float meany = wm * invBN + bres[o];
    float wMw = 0.f;
    for (int c = 0; c < 64; c++) {
        float t = 0.f;
        for (int c2 = 0; c2 < 64; c2++) t += w[o * 64 + c2] * g_cov[c * 64 + c2];
        wMw += w[o * 64 + c] * t;
    }
    float Ey2 = wMw * invBN + 2.f * bres[o] * (wm * invBN) + bres[o] * bres[o];
    float var = Ey2 - meany * meany;
    float A = gres[o] * (1.0f / sqrtf(var + 1e-5f));
    g_A[o] = A;
    g_Bc[o] = beres[o] - meany * A;
}

// ---------------- K5: radius ball query (lowest-index hits, warp per center) ----------------
__global__ __launch_bounds__(128) void ball_kernel(const float* __restrict__ loc) {
    int gw = blockIdx.x * 4 + (threadIdx.x >> 5);   // 0..1023
    int lane = threadIdx.x & 31;
    int b = gw >> 6, s = gw & 63;
    const float* lb = loc + (size_t)b * 3 * NN;
    float cx = g_fploc[(b * 3 + 0) * SS + s];
    float cy = g_fploc[(b * 3 + 1) * SS + s];
    float cz = g_fploc[(b * 3 + 2) * SS + s];
    float ss = sq3(cx, cy, cz);
    int* gi = g_gidx + (b * SS + s) * KK;
    int total = 0;
    for (int n0 = 0; n0 < NN; n0 += 32) {
        int p = n0 + lane;
        float x = lb[p], y = lb[NN + p], z = lb[2 * NN + p];
        float sq = __fadd_rn(__fadd_rn(__fmul_rn(-2.0f, dot3fma(cx, cy, cz, x, y, z)), ss),
                             sq3(x, y, z));
        bool hit = !(sq > 0.09f);
        unsigned m = __ballot_sync(0xffffffffu, hit);
        int pos = total + __popc(m & ((1u << lane) - 1u));
        if (hit && pos < KK) gi[pos] = p;
        total += __popc(m);
        if (total >= KK) break;
    }
    __syncwarp();
    if (total < KK) {
        int first = (total > 0) ? gi[0] : 0;
        for (int j = total + lane; j < KK; j += 32) gi[j] = first;
    }
}

// ---------------- K6: node offset / node loc (block per (b,s), thread per k) ----------------
__global__ __launch_bounds__(64) void node_kernel(const float* __restrict__ loc,
                                                  const float* __restrict__ woff,
                                                  float* __restrict__ out) {
    int b = blockIdx.x >> 6, s = blockIdx.x & 63;
    int k = threadIdx.x;   // 64
    __shared__ float swoff[192];
    __shared__ float sfpf[64];
    __shared__ float part[6];
    sfpf[k] = g_fpfea[(b * CC + k) * SS + s];
    for (int j = k; j < 192; j += 64) swoff[j] = woff[j];
    __syncthreads();

    int p = g_gidx[(b * SS + s) * KK + k];
    const float* lb = loc + (size_t)b * 3 * NN;
    float flx = g_fploc[(b * 3 + 0) * SS + s];
    float fly = g_fploc[(b * 3 + 1) * SS + s];
    float flz = g_fploc[(b * 3 + 2) * SS + s];
    float dlx = lb[p] - flx, dly = lb[NN + p] - fly, dlz = lb[2 * NN + p] - flz;

    const float* fr = g_feaT + ((size_t)b * NN + p) * CC;
    float s0 = 0.f, s1 = 0.f, s2 = 0.f;
#pragma unroll
    for (int c = 0; c < 64; c++) {
        float df = fr[c] - sfpf[c];
        s0 += swoff[c] * df;
        s1 += swoff[64 + c] * df;
        s2 += swoff[128 + c] * df;
    }
    float t0 = tanhf(s0) * dlx, t1 = tanhf(s1) * dly, t2 = tanhf(s2) * dlz;
    unsigned lane = k & 31, w = k >> 5;
#pragma unroll
    for (int off = 16; off; off >>= 1) {
        t0 += __shfl_down_sync(0xffffffffu, t0, off);
        t1 += __shfl_down_sync(0xffffffffu, t1, off);
        t2 += __shfl_down_sync(0xffffffffu, t2, off);
    }
    if (lane == 0) { part[w * 3 + 0] = t0; part[w * 3 + 1] = t1; part[w * 3 + 2] = t2; }
    __syncthreads();
    if (k == 0) {
        float m0 = (part[0] + part[3]) * (1.f / 64.f);
        float m1 = (part[1] + part[4]) * (1.f / 64.f);
        float m2 = (part[2] + part[5]) * (1.f / 64.f);
        out[OFF_NO + (b * 3 + 0) * SS + s] = m0;
        out[OFF_NO + (b * 3 + 1) * SS + s] = m1;
        out[OFF_NO + (b * 3 + 2) * SS + s] = m2;
        float nx = flx + m0, ny = fly + m1, nz = flz + m2;
        g_nodeloc[(b * 3 + 0) * SS + s] = nx;
        g_nodeloc[(b * 3 + 1) * SS + s] = ny;
        g_nodeloc[(b * 3 + 2) * SS + s] = nz;
        g_nodesq[b * SS + s] = sq3(nx, ny, nz);
    }
}

// ---------------- K7: fused 64-NN + residual-BN-ReLU + max (block per (b,s)) ----------------
// Register-resident per-thread sorted top-16, then warp-0 tournament over 256 list heads.
__global__ __launch_bounds__(256) void nodefea_kernel(const float* __restrict__ loc,
                                                      const float* __restrict__ wres,
                                                      const float* __restrict__ bres,
                                                      float* __restrict__ out) {
    __shared__ __align__(16) unsigned char pool[4096 * 4 + 4096 * 4 + 64 * 4];  // 33 KB
    __shared__ float smax[256];
    float* slv = (float*)pool;            // [256][16] values
    int*   sli = (int*)(pool + 16384);    // [256][16] indices
    int*   ssel = (int*)(pool + 32768);   // [64] selected point indices

    int b = blockIdx.x >> 6, s = blockIdx.x & 63;
    int tid = threadIdx.x;
    const float* lb = loc + (size_t)b * 3 * NN;
    float nx = g_nodeloc[(b * 3 + 0) * SS + s];
    float ny = g_nodeloc[(b * 3 + 1) * SS + s];
    float nz = g_nodeloc[(b * 3 + 2) * SS + s];
    float nsq = g_nodesq[b * SS + s];

    // phase A: per-thread sorted top-16 over its 64 strided candidates
    float lv[16];
    int   li[16];
#pragma unroll
    for (int i = 0; i < 16; i++) { lv[i] = 3.402823466e38f; li[i] = 0x7fffffff; }
#pragma unroll 4
    for (int j = 0; j < 64; j++) {
        int p = tid + (j << 8);
        float x = lb[p], y = lb[NN + p], z = lb[2 * NN + p];
        float d = __fadd_rn(__fadd_rn(__fmul_rn(-2.0f, dot3fma(nx, ny, nz, x, y, z)), nsq),
                            sq3(x, y, z));
        if (d < lv[15]) {
            lv[15] = d; li[15] = p;
#pragma unroll
            for (int i = 15; i > 0; --i) {
                if (lv[i] < lv[i - 1]) {
                    float tv = lv[i]; lv[i] = lv[i - 1]; lv[i - 1] = tv;
                    int   ti = li[i]; li[i] = li[i - 1]; li[i - 1] = ti;
                }
            }
        }
    }
#pragma unroll
    for (int i = 0; i < 16; i++) { slv[tid * 16 + i] = lv[i]; sli[tid * 16 + i] = li[i]; }
    __syncthreads();

    // phase B: warp 0 tournament — 64 rounds of lexicographic argmin over 256 heads
    if (tid < 32) {
        int L = tid;
        float hv[8]; int hi[8]; int ptr[8];
#pragma unroll
        for (int k = 0; k < 8; k++) {
            ptr[k] = 0;
            hv[k] = slv[(L * 8 + k) * 16];
            hi[k] = sli[(L * 8 + k) * 16];
        }
        float mv = hv[0]; int mi = hi[0]; int mk = 0;
#pragma unroll
        for (int k = 1; k < 8; k++)
            if (hv[k] < mv || (hv[k] == mv && hi[k] < mi)) { mv = hv[k]; mi = hi[k]; mk = k; }

        for (int r = 0; r < KK; r++) {
            float wv = mv; int wi = mi;
#pragma unroll
            for (int off = 16; off; off >>= 1) {
                float ov = __shfl_xor_sync(0xffffffffu, wv, off);
                int   oi = __shfl_xor_sync(0xffffffffu, wi, off);
                if (ov < wv || (ov == wv && oi < wi)) { wv = ov; wi = oi; }
            }
            if (L == 0) ssel[r] = wi;
            if (mv == wv && mi == wi) {        // exactly one owner (indices unique)
#pragma unroll
                for (int k = 0; k < 8; k++)
                    if (k == mk) {
                        int np = ++ptr[k];
                        bool ok = np < 16;
                        hv[k] = ok ? slv[(L * 8 + k) * 16 + np] : 3.402823466e38f;
                        hi[k] = ok ? sli[(L * 8 + k) * 16 + np] : 0x7fffffff;
                    }
                mv = hv[0]; mi = hi[0]; mk = 0;
#pragma unroll
                for (int k = 1; k < 8; k++)
                    if (hv[k] < mv || (hv[k] == mv && hi[k] < mi)) { mv = hv[k]; mi = hi[k]; mk = k; }
            }
        }
    }
    __syncthreads();

    // phase C: gather features (point-contiguous rows) into smem, GEMV (f32x2), BN+ReLU, max
    float* gf = (float*)pool;   // [64][68] — lists region is dead now; ssel is beyond it
    for (int idx = tid; idx < 1024; idx += 256) {
        int k = idx >> 4, seg = idx & 15;
        int p = ssel[k];
        float4 v = *(const float4*)(g_feaT + ((size_t)b * NN + p) * CC + seg * 4);
        *(float4*)&gf[k * 68 + seg * 4] = v;
    }
    __syncthreads();

    int o = tid & 63, kq = tid >> 6;
    unsigned long long wp2[32];
    {
        const ulonglong2* wp = (const ulonglong2*)(wres + o * 64);
#pragma unroll
        for (int i = 0; i < 16; i++) {
            ulonglong2 v = wp[i];
            wp2[2 * i] = v.x; wp2[2 * i + 1] = v.y;
        }
    }
    float A = g_A[o], Bc = g_Bc[o], bv0 = bres[o];
    float mx = -3.402823466e38f;
    for (int j = 0; j < 16; j++) {
        int k = kq * 16 + j;
        const ulonglong2* gp = (const ulonglong2*)(gf + k * 68);
        unsigned long long acc = 0ull;
#pragma unroll
        for (int i = 0; i < 16; i++) {
            ulonglong2 g2 = gp[i];
            acc = fma2(wp2[2 * i], g2.x, acc);
            acc = fma2(wp2[2 * i + 1], g2.y, acc);
        }
        float lo, hi2;
        unpack2(acc, lo, hi2);
        float y = lo + hi2;
        float v = fmaxf(0.f, A * (y + bv0) + Bc);
        mx = fmaxf(mx, v);
    }
    smax[tid] = mx;
    __syncthreads();
    if (tid < 64) {
        float m = fmaxf(fmaxf(smax[tid], smax[tid + 64]), fmaxf(smax[tid + 128], smax[tid + 192]));
        out[OFF_NF + (b * CC + tid) * SS + s] = m;
    }
}

// ---------------- K8: 3-NN inverse-distance interpolation + concat copy ----------------
__global__ __launch_bounds__(256) void upsample_kernel(const float* __restrict__ loc,
                                                       const float* __restrict__ fea,
                                                       float* __restrict__ out) {
    __shared__ float snx[64], sny[64], snz[64], snq[64];
    __shared__ float snf[64 * 68];   // [m][c], pad 68
    int b = blockIdx.y;
    int n = blockIdx.x * 256 + threadIdx.x;
    int tid = threadIdx.x;
    if (tid < 64) {
        snx[tid] = g_nodeloc[(b * 3 + 0) * SS + tid];
        sny[tid] = g_nodeloc[(b * 3 + 1) * SS + tid];
        snz[tid] = g_nodeloc[(b * 3 + 2) * SS + tid];
        snq[tid] = g_nodesq[b * SS + tid];
    }
    for (int idx = tid; idx < 4096; idx += 256) {
        int m = idx & 63, c = idx >> 6;
        snf[m * 68 + c] = out[OFF_NF + (b * CC + c) * SS + m];
    }
    __syncthreads();

    const float* lb = loc + (size_t)b * 3 * NN;
    float x = lb[n], y = lb[NN + n], z = lb[2 * NN + n];
    float psq = sq3(x, y, z);

    float d0 = 3.402823466e38f, d1 = d0, d2 = d0;
    int i0 = 0, i1 = 0, i2 = 0;
#pragma unroll 8
    for (int m = 0; m < 64; m++) {
        float d = __fadd_rn(
            __fadd_rn(__fmul_rn(-2.0f, dot3fma(x, y, z, snx[m], sny[m], snz[m])), psq),
            snq[m]);
        if (d < d0)      { d2 = d1; i2 = i1; d1 = d0; i1 = i0; d0 = d; i0 = m; }
        else if (d < d1) { d2 = d1; i2 = i1; d1 = d; i1 = m; }
        else if (d < d2) { d2 = d; i2 = m; }
    }
    float w0 = 1.0f / fmaxf(d0, 1e-10f);
    float w1 = 1.0f / fmaxf(d1, 1e-10f);
    float w2 = 1.0f / fmaxf(d2, 1e-10f);
    float wsum = w0 + w1 + w2;
    w0 /= wsum; w1 /= wsum; w2 /= wsum;

    const float* fb = fea + (size_t)b * CC * NN;
    float* ob = out + (size_t)b * 128 * NN;
#pragma unroll 8
    for (int c = 0; c < 64; c++) {
        float ip = snf[i0 * 68 + c] * w0 + snf[i1 * 68 + c] * w1 + snf[i2 * 68 + c] * w2;
        ob[(64 + c) * NN + n] = ip;
        ob[c * NN + n] = fb[c * NN + n];
    }
}

// ---------------- launch ----------------
extern "C" void kernel_launch(void* const* d_in, const int* in_sizes, int n_in,
                              void* d_out, int out_size) {
    const float* fea   = (const float*)d_in[0];
    const float* loc   = (const float*)d_in[1];
    const float* wres  = (const float*)d_in[2];
    const float* bres  = (const float*)d_in[3];
    const float* gres  = (const float*)d_in[4];
    const float* beres = (const float*)d_in[5];
    const float* woff  = (const float*)d_in[6];
    float* out = (float*)d_out;

    cudaFuncSetAttribute(fps_kernel, cudaFuncAttributeMaxDynamicSharedMemorySize, 3 * NN * 4);

    fps_kernel<<<BB, 1024, 3 * NN * 4>>>(loc, fea);
    transpose_kernel<<<dim3(NN / 32, CC / 32, BB), dim3(32, 8)>>>(fea);
    cov_kernel<<<NCOV, 256>>>();
    covred1_kernel<<<130, 256>>>();
    covred2_kernel<<<17, 256>>>();
    bn_kernel<<<1, 64>>>(wres, bres, gres, beres);
    ball_kernel<<<256, 128>>>(loc);
    node_kernel<<<BB * SS, 64>>>(loc, woff, out);
    nodefea_kernel<<<BB * SS, 256>>>(loc, wres, bres, out);
    upsample_kernel<<<dim3(NN / 256, BB), 256>>>(loc, fea, out);
}